// round 15
// baseline (speedup 1.0000x reference)
#include <cuda_runtime.h>
#include <cstdint>

#define Bsz 128
#define Lseq 1024
#define Hd 256
#define G3 768
#define W2S 258   // u64 stride per duplicated-weight row

typedef unsigned long long u64;

__device__ __forceinline__ u64 f2fma(u64 a, u64 b, u64 c) {
    u64 d; asm("fma.rn.f32x2 %0, %1, %2, %3;" : "=l"(d) : "l"(a), "l"(b), "l"(c)); return d;
}
__device__ __forceinline__ u64 f2add(u64 a, u64 b) {
    u64 d; asm("add.rn.f32x2 %0, %1, %2;" : "=l"(d) : "l"(a), "l"(b)); return d;
}
__device__ __forceinline__ u64 dup2(float x) {
    u64 r; asm("mov.b64 %0, {%1, %1};" : "=l"(r) : "f"(x)); return r;
}
__device__ __forceinline__ void up2(u64 v, float& lo, float& hi) {
    asm("mov.b64 {%0, %1}, %2;" : "=f"(lo), "=f"(hi) : "l"(v));
}

// ---------------- scratch ----------------
__device__ float g_gi[(size_t)Lseq * G3 * Bsz];      // layer-0 input gates [t][3H][B]
__device__ float g_gi1[(size_t)Lseq * G3 * Bsz];     // layer-1 input gates [t][3H][B]
__device__ float g_hseq0[(size_t)Lseq * Hd * Bsz];   // [t][k][b]
__device__ float g_hseq1[(size_t)Lseq * Hd * Bsz];

__device__ unsigned g_flagA[4 * 32 * 32];   // layer-0 h progress (monotonic)
__device__ unsigned g_flagB[4 * 32 * 32];   // layer-1 h progress (monotonic)
__device__ unsigned g_giflag[Lseq * 12];    // gi1 tile-ready flags (== epoch)
__device__ unsigned g_epoch = 0;

__global__ void epoch_kernel() {
    if (threadIdx.x == 0 && blockIdx.x == 0) g_epoch = g_epoch + 1u;
}

// ---------------- input-side GEMM (layer 0): Gi[t][c][b] ----------------
__global__ __launch_bounds__(256) void gi_gemm_kernel(
    const float* __restrict__ xin, const float* __restrict__ W,
    const float* __restrict__ bias)
{
    __shared__ float Ws[16 * 132];
    __shared__ float As[16 * 132];

    const int t  = blockIdx.y;
    const int c0 = blockIdx.x * 128;
    const int tid = threadIdx.x;
    const int ty = tid >> 4;
    const int tx = tid & 15;

    u64 acc2[8][4];
#pragma unroll
    for (int i = 0; i < 8; i++)
#pragma unroll
        for (int j = 0; j < 4; j++) acc2[i][j] = 0ull;

    for (int k0 = 0; k0 < 256; k0 += 16) {
        {
            int row  = tid >> 2;
            int col4 = (tid & 3) * 4;
#pragma unroll
            for (int it = 0; it < 2; it++, row += 64) {
                float4 w = *(const float4*)(W + (size_t)(c0 + row) * 256 + k0 + col4);
                Ws[(col4 + 0) * 132 + row] = w.x;
                Ws[(col4 + 1) * 132 + row] = w.y;
                Ws[(col4 + 2) * 132 + row] = w.z;
                Ws[(col4 + 3) * 132 + row] = w.w;
            }
        }
        {
            int row  = tid >> 2;
            int col4 = (tid & 3) * 4;
#pragma unroll
            for (int it = 0; it < 2; it++, row += 64) {
                float4 a = *(const float4*)(xin + ((size_t)row * Lseq + t) * 256 + k0 + col4);
                As[(col4 + 0) * 132 + row] = a.x;
                As[(col4 + 1) * 132 + row] = a.y;
                As[(col4 + 2) * 132 + row] = a.z;
                As[(col4 + 3) * 132 + row] = a.w;
            }
        }
        __syncthreads();

#pragma unroll
        for (int kk = 0; kk < 16; kk++) {
            float wr[8];
            *(float4*)(wr)     = *(const float4*)(Ws + kk * 132 + ty * 4);
            *(float4*)(wr + 4) = *(const float4*)(Ws + kk * 132 + 64 + ty * 4);
            ulonglong2 aA = *(const ulonglong2*)(As + kk * 132 + tx * 4);
            ulonglong2 aB = *(const ulonglong2*)(As + kk * 132 + 64 + tx * 4);
#pragma unroll
            for (int i = 0; i < 8; i++) {
                u64 wd = dup2(wr[i]);
                acc2[i][0] = f2fma(aA.x, wd, acc2[i][0]);
                acc2[i][1] = f2fma(aA.y, wd, acc2[i][1]);
                acc2[i][2] = f2fma(aB.x, wd, acc2[i][2]);
                acc2[i][3] = f2fma(aB.y, wd, acc2[i][3]);
            }
        }
        __syncthreads();
    }

    float* gout = g_gi + (size_t)t * G3 * Bsz;
#pragma unroll
    for (int i = 0; i < 8; i++) {
        int c = (i < 4) ? (c0 + ty * 4 + i) : (c0 + 64 + ty * 4 + (i - 4));
        float bv = bias[c];
        float a0, a1, a2, a3, a4, a5, a6, a7;
        up2(acc2[i][0], a0, a1); up2(acc2[i][1], a2, a3);
        up2(acc2[i][2], a4, a5); up2(acc2[i][3], a6, a7);
        *(float4*)(gout + (size_t)c * Bsz + tx * 4) =
            make_float4(a0 + bv, a1 + bv, a2 + bv, a3 + bv);
        *(float4*)(gout + (size_t)c * Bsz + 64 + tx * 4) =
            make_float4(a4 + bv, a5 + bv, a6 + bv, a7 + bv);
    }
}

// ---------------- mega kernel: recur0 || recur1 || gemm1 ----------------
// bids 0-127:   layer-0 recurrence (dataflow flags, direct-LDG dot)
// bids 128-255: layer-1 recurrence (gi from g_gi1, gated by g_giflag)
// bids 256+:    gemm1 scavenger tiles (gi1 = W_ih1 . h0(t) + b_ih1)
__global__ __launch_bounds__(512, 2) void gru_mega_kernel(
    const float* __restrict__ w_hh0, const float* __restrict__ b_hh0,
    const float* __restrict__ w_hh1, const float* __restrict__ b_hh1,
    const float* __restrict__ w_ih1, const float* __restrict__ b_ih1,
    const float* __restrict__ h0all)
{
    extern __shared__ __align__(16) char smraw[];
    const int tid = threadIdx.x;
    const unsigned E  = *(volatile unsigned*)&g_epoch;
    const unsigned FB = E * 2048u;

    if (blockIdx.x >= 256) {
        // ============ scavenger: gi1 tiles (64c x 128b x 4t) ============
        float* Ws = (float*)smraw;        // 16k x 64c, stride 68
        float* As = Ws + 16 * 68;         // 16k x 128b, stride 132
        const int g  = (int)blockIdx.x - 256;
        const int ct = g % 12;
        const int tb = g / 12;
        const int c0s = ct * 64;
        const int ty = (tid & 255) >> 4;
        const int tx = tid & 15;

        for (int tt = 0; tt < 4; tt++) {
            const int t = tb * 4 + tt;
            if (tid < 128) {
                const unsigned* fp = &g_flagA[tid * 32];
                unsigned v;
                for (;;) {
                    asm volatile("ld.acquire.gpu.u32 %0, [%1];" : "=r"(v) : "l"(fp) : "memory");
                    if (v >= FB + (unsigned)(t + 1)) break;
                    __nanosleep(2000);
                }
            }
            __syncthreads();

            u64 acc2[4][4];
#pragma unroll
            for (int i = 0; i < 4; i++)
#pragma unroll
                for (int q = 0; q < 4; q++) acc2[i][q] = 0ull;

            const float* hsrc = g_hseq0 + (size_t)t * (Hd * Bsz);
            for (int k0 = 0; k0 < 256; k0 += 16) {
                for (int i = tid; i < 1024; i += 512) {
                    int row = i >> 4, kk = i & 15;
                    Ws[kk * 68 + row] = w_ih1[(size_t)(c0s + row) * 256 + k0 + kk];
                }
                for (int i = tid; i < 2048; i += 512) {
                    int k = i >> 7, b = i & 127;
                    As[k * 132 + b] = hsrc[(size_t)(k0 + k) * 128 + b];
                }
                __syncthreads();
                if (tid < 256) {
#pragma unroll
                    for (int kk = 0; kk < 16; kk++) {
                        float wr[4];
                        wr[0] = Ws[kk * 68 + ty * 4 + 0];
                        wr[1] = Ws[kk * 68 + ty * 4 + 1];
                        wr[2] = Ws[kk * 68 + ty * 4 + 2];
                        wr[3] = Ws[kk * 68 + ty * 4 + 3];
                        ulonglong2 aA = *(const ulonglong2*)(As + kk * 132 + tx * 4);
                        ulonglong2 aB = *(const ulonglong2*)(As + kk * 132 + 64 + tx * 4);
#pragma unroll
                        for (int i = 0; i < 4; i++) {
                            u64 wd = dup2(wr[i]);
                            acc2[i][0] = f2fma(aA.x, wd, acc2[i][0]);
                            acc2[i][1] = f2fma(aA.y, wd, acc2[i][1]);
                            acc2[i][2] = f2fma(aB.x, wd, acc2[i][2]);
                            acc2[i][3] = f2fma(aB.y, wd, acc2[i][3]);
                        }
                    }
                }
                __syncthreads();
            }
            if (tid < 256) {
                float* gout = g_gi1 + (size_t)t * (G3 * Bsz);
#pragma unroll
                for (int i = 0; i < 4; i++) {
                    int c = c0s + ty * 4 + i;
                    float bv = b_ih1[c];
                    float a0, a1, a2, a3, a4, a5, a6, a7;
                    up2(acc2[i][0], a0, a1); up2(acc2[i][1], a2, a3);
                    up2(acc2[i][2], a4, a5); up2(acc2[i][3], a6, a7);
                    *(float4*)(gout + (size_t)c * Bsz + tx * 4) =
                        make_float4(a0 + bv, a1 + bv, a2 + bv, a3 + bv);
                    *(float4*)(gout + (size_t)c * Bsz + 64 + tx * 4) =
                        make_float4(a4 + bv, a5 + bv, a6 + bv, a7 + bv);
                }
            }
            __syncthreads();
            if (tid == 0) {
                asm volatile("st.release.gpu.u32 [%0], %1;"
                             :: "l"(&g_giflag[t * 12 + ct]), "r"(E) : "memory");
            }
        }
        return;
    }

    // ============ recurrence (both layers), direct-LDG dot ============
    u64*   w2_s  = (u64*)smraw;            // 24*258 = 6192 u64
    u64*   red_s = w2_s + 6192;            // 8 kq * 384 = 3072 u64
    float* bh_s  = (float*)(red_s + 3072); // 24 floats (+pad to 32)

    const int layer = (int)blockIdx.x >> 7;
    const int bid7  = (int)blockIdx.x & 127;
    const int bt = bid7 >> 5;
    const int ht = bid7 & 31;
    const int b0 = bt * 32;
    const int j0 = ht * 8;

    const float* w_hh = layer ? w_hh1 : w_hh0;
    const float* b_hh = layer ? b_hh1 : b_hh0;
    float* hseq = layer ? g_hseq1 : g_hseq0;
    unsigned* flags = layer ? g_flagB : g_flagA;
    unsigned* myflag = &flags[(bt * 32 + ht) * 32];
    const float* gi_src = layer ? g_gi1 : g_gi;
    const float* h0g = h0all + (size_t)layer * Bsz * Hd;   // [b][k]

    const int ct0 = j0 >> 6;   // gi tile column (layer 1 gating)

    // duplicated persistent weights
    for (int idx = tid; idx < 6144; idx += 512) {
        int gj = idx >> 8;
        int k  = idx & 255;
        int g  = gj >> 3, j = gj & 7;
        w2_s[gj * W2S + k] = dup2(__ldg(w_hh + (size_t)(g * 256 + j0 + j) * 256 + k));
    }
    if (tid < 24) {
        int g = tid >> 3, j = tid & 7;
        bh_s[tid] = b_hh[g * 256 + j0 + j];
    }
    __syncthreads();

    const int bq = tid & 7;
    const int j  = (tid >> 3) & 7;
    const int kq = tid >> 6;
    const int kbase = kq * 32;

    const u64* wrp = w2_s + (0 + j) * W2S + kbase;
    const u64* wzp = w2_s + (8 + j) * W2S + kbase;
    const u64* wnp = w2_s + (16 + j) * W2S + kbase;
    const int boff = b0 + bq * 4;

    // merged reduce+act mapping (tid < 128): aj = hidden unit, bp = batch pair
    const int aj = tid >> 4;
    const int bp = tid & 15;
    const size_t gidx2 = (size_t)(j0 + aj) * Bsz + b0 + 2 * bp;

    float2 cir2 = make_float2(0.f, 0.f), ciz2 = cir2, cin2 = cir2;
    if (tid < 128) {
        if (layer) {
            unsigned v;
#pragma unroll
            for (int e = 0; e < 3; e++) {
                const unsigned* fp = &g_giflag[0 * 12 + 4 * e + ct0];
                do {
                    asm volatile("ld.acquire.gpu.u32 %0, [%1];" : "=r"(v) : "l"(fp) : "memory");
                } while (v < E);
            }
        }
        cir2 = *(const float2*)(gi_src + gidx2);
        ciz2 = *(const float2*)(gi_src + 32768 + gidx2);
        cin2 = *(const float2*)(gi_src + 65536 + gidx2);
    }

    for (int t = 0; t < Lseq; t++) {
        // ---- wait for the 4 producer chunks covering this thread's k-range ----
        if (t > 0) {
#pragma unroll
            for (int e = 0; e < 4; e++) {
                const unsigned* fp = &flags[(bt * 32 + kq * 4 + e) * 32];
                unsigned v;
                do {
                    asm volatile("ld.acquire.gpu.u32 %0, [%1];" : "=r"(v) : "l"(fp) : "memory");
                } while (v < FB + (unsigned)t);
            }
        }

        // ---- partial dot over this thread's 32 k (h via direct LDG) ----
        u64 ar0 = 0, ar1 = 0, az0 = 0, az1 = 0, an0 = 0, an1 = 0;
        if (t == 0) {
#pragma unroll
            for (int i = 0; i < 32; i += 2) {
                int k = kbase + i;
                float4 ha4, hc4;
                ha4.x = h0g[(size_t)(boff + 0) * 256 + k];
                ha4.y = h0g[(size_t)(boff + 1) * 256 + k];
                ha4.z = h0g[(size_t)(boff + 2) * 256 + k];
                ha4.w = h0g[(size_t)(boff + 3) * 256 + k];
                hc4.x = h0g[(size_t)(boff + 0) * 256 + k + 1];
                hc4.y = h0g[(size_t)(boff + 1) * 256 + k + 1];
                hc4.z = h0g[(size_t)(boff + 2) * 256 + k + 1];
                hc4.w = h0g[(size_t)(boff + 3) * 256 + k + 1];
                const u64* ha = (const u64*)&ha4;
                const u64* hc = (const u64*)&hc4;
                ulonglong2 wr = *(const ulonglong2*)(wrp + i);
                ulonglong2 wz = *(const ulonglong2*)(wzp + i);
                ulonglong2 wn = *(const ulonglong2*)(wnp + i);
                ar0 = f2fma(ha[0], wr.x, ar0); ar1 = f2fma(ha[1], wr.x, ar1);
                ar0 = f2fma(hc[0], wr.y, ar0); ar1 = f2fma(hc[1], wr.y, ar1);
                az0 = f2fma(ha[0], wz.x, az0); az1 = f2fma(ha[1], wz.x, az1);
                az0 = f2fma(hc[0], wz.y, az0); az1 = f2fma(hc[1], wz.y, az1);
                an0 = f2fma(ha[0], wn.x, an0); an1 = f2fma(ha[1], wn.x, an1);
                an0 = f2fma(hc[0], wn.y, an0); an1 = f2fma(hc[1], wn.y, an1);
            }
        } else {
            const float* hsrc = hseq + (size_t)(t - 1) * (Hd * Bsz) + boff;
#pragma unroll 8
            for (int i = 0; i < 32; i += 2) {
                int k = kbase + i;
                float4 ha4 = *(const float4*)(hsrc + (size_t)k * Bsz);
                float4 hc4 = *(const float4*)(hsrc + (size_t)(k + 1) * Bsz);
                const u64* ha = (const u64*)&ha4;
                const u64* hc = (const u64*)&hc4;
                ulonglong2 wr = *(const ulonglong2*)(wrp + i);
                ulonglong2 wz = *(const ulonglong2*)(wzp + i);
                ulonglong2 wn = *(const ulonglong2*)(wnp + i);
                ar0 = f2fma(ha[0], wr.x, ar0); ar1 = f2fma(ha[1], wr.x, ar1);
                ar0 = f2fma(hc[0], wr.y, ar0); ar1 = f2fma(hc[1], wr.y, ar1);
                az0 = f2fma(ha[0], wz.x, az0); az1 = f2fma(ha[1], wz.x, az1);
                az0 = f2fma(hc[0], wz.y, az0); az1 = f2fma(hc[1], wz.y, az1);
                an0 = f2fma(ha[0], wn.x, an0); an1 = f2fma(ha[1], wn.x, an1);
                an0 = f2fma(hc[0], wn.y, an0); an1 = f2fma(hc[1], wn.y, an1);
            }
        }
        {
            u64* rb = red_s + (size_t)kq * 384 + (j * 8 + bq) * 2;
            *(ulonglong2*)(rb)       = make_ulonglong2(ar0, ar1);
            *(ulonglong2*)(rb + 128) = make_ulonglong2(az0, az1);
            *(ulonglong2*)(rb + 256) = make_ulonglong2(an0, an1);
        }
        __syncthreads();

        // ---- merged reduce + activation (128 threads: 8 j x 16 b-pairs) ----
        if (tid < 128) {
            const u64* base = red_s + aj * 16 + bp;
            u64 sr = 0, sz = 0, sn = 0;
#pragma unroll
            for (int q = 0; q < 8; q++) {
                sr = f2add(sr, base[q * 384]);
                sz = f2add(sz, base[q * 384 + 128]);
                sn = f2add(sn, base[q * 384 + 256]);
            }
            float gr0, gr1, gz0, gz1, gn0, gn1;
            up2(sr, gr0, gr1); up2(sz, gz0, gz1); up2(sn, gn0, gn1);
            float bhr = bh_s[aj], bhz = bh_s[8 + aj], bhn = bh_s[16 + aj];

            float2 hp;
            if (t == 0) {
                hp.x = h0g[(size_t)(b0 + 2 * bp) * 256 + j0 + aj];
                hp.y = h0g[(size_t)(b0 + 2 * bp + 1) * 256 + j0 + aj];
            } else {
                hp = *(const float2*)(hseq + (size_t)(t - 1) * (Hd * Bsz) + gidx2);
            }

            float r0 = 1.0f / (1.0f + __expf(-(cir2.x + gr0 + bhr)));
            float r1 = 1.0f / (1.0f + __expf(-(cir2.y + gr1 + bhr)));
            float z0 = 1.0f / (1.0f + __expf(-(ciz2.x + gz0 + bhz)));
            float z1 = 1.0f / (1.0f + __expf(-(ciz2.y + gz1 + bhz)));
            float n0 = tanhf(cin2.x + r0 * (gn0 + bhn));
            float n1 = tanhf(cin2.y + r1 * (gn1 + bhn));
            float hn0 = (1.0f - z0) * n0 + z0 * hp.x;
            float hn1 = (1.0f - z1) * n1 + z1 * hp.y;

            *(float2*)(hseq + (size_t)t * (Hd * Bsz) + gidx2) = make_float2(hn0, hn1);
        }
        __syncthreads();

        if (tid == 0) {
            asm volatile("st.release.gpu.u32 [%0], %1;"
                         :: "l"(myflag), "r"(FB + (unsigned)(t + 1)) : "memory");
        }
        if (tid < 128 && t + 1 < Lseq) {
            if (layer) {
                unsigned v;
#pragma unroll
                for (int e = 0; e < 3; e++) {
                    const unsigned* fp = &g_giflag[(t + 1) * 12 + 4 * e + ct0];
                    do {
                        asm volatile("ld.acquire.gpu.u32 %0, [%1];" : "=r"(v) : "l"(fp) : "memory");
                    } while (v < E);
                }
            }
            const float* gi_n = gi_src + (size_t)(t + 1) * (G3 * Bsz);
            cir2 = *(const float2*)(gi_n + gidx2);
            ciz2 = *(const float2*)(gi_n + 32768 + gidx2);
            cin2 = *(const float2*)(gi_n + 65536 + gidx2);
        }
    }
}

// ---------------- transpose g_hseq1 [t][h][b] -> out [b][t][h] ----------------
__global__ __launch_bounds__(256) void transpose_out_kernel(float* __restrict__ out)
{
    __shared__ float tile[32 * 129];
    const int t  = blockIdx.y;
    const int h0 = blockIdx.x * 32;
    const int tid = threadIdx.x;
    const float* src = g_hseq1 + (size_t)t * (Hd * Bsz) + (size_t)h0 * Bsz;

    for (int idx = tid; idx < 4096; idx += 256) {
        int hh = idx >> 7, bb = idx & 127;
        tile[hh * 129 + bb] = src[idx];
    }
    __syncthreads();
    for (int idx = tid; idx < 4096; idx += 256) {
        int bb = idx >> 5, hh = idx & 31;
        out[(size_t)bb * Lseq * Hd + (size_t)t * Hd + h0 + hh] = tile[hh * 129 + bb];
    }
}

// ---------------- final hidden states ----------------
__global__ __launch_bounds__(256) void hn_kernel(float* __restrict__ out)
{
    int idx = blockIdx.x * blockDim.x + threadIdx.x;  // 0..65535
    int layer = idx >> 15;
    int b = (idx >> 8) & 127;
    int h = idx & 255;
    const float* hs = layer ? g_hseq1 : g_hseq0;
    out[(size_t)Bsz * Lseq * Hd + idx] =
        hs[(size_t)(Lseq - 1) * (Hd * Bsz) + (size_t)h * Bsz + b];
}

// ---------------- launcher ----------------
extern "C" void kernel_launch(void* const* d_in, const int* in_sizes, int n_in,
                              void* d_out, int out_size)
{
    const float* x     = (const float*)d_in[0];
    const float* h0    = (const float*)d_in[1];
    const float* w_ih0 = (const float*)d_in[2];
    const float* w_hh0 = (const float*)d_in[3];
    const float* b_ih0 = (const float*)d_in[4];
    const float* b_hh0 = (const float*)d_in[5];
    const float* w_ih1 = (const float*)d_in[6];
    const float* w_hh1 = (const float*)d_in[7];
    const float* b_ih1 = (const float*)d_in[8];
    const float* b_hh1 = (const float*)d_in[9];
    float* out = (float*)d_out;

    const size_t smem = (6192 + 3072) * sizeof(u64) + 32 * sizeof(float);  // ~74.2 KB
    cudaFuncSetAttribute(gru_mega_kernel,
                         cudaFuncAttributeMaxDynamicSharedMemorySize, (int)smem);

    epoch_kernel<<<1, 32>>>();
    gi_gemm_kernel<<<dim3(6, Lseq), 256>>>(x, w_ih0, b_ih0);
    // recur0 (0-127) || recur1 (128-255) || gemm1 scavengers (256..3327)
    gru_mega_kernel<<<256 + 3072, 512, smem>>>(w_hh0, b_hh0, w_hh1, b_hh1,
                                               w_ih1, b_ih1, h0);
    transpose_out_kernel<<<dim3(8, Lseq), 256>>>(out);
    if (out_size >= (int)((size_t)Bsz * Lseq * Hd + 2 * Bsz * Hd))
        hn_kernel<<<256, 256>>>(out);
}

// round 16
// speedup vs baseline: 1.3080x; 1.3080x over previous
#include <cuda_runtime.h>
#include <cstdint>

#define Bsz 128
#define Lseq 1024
#define Hd 256
#define G3 768
#define W2S 258   // u64 stride per duplicated-weight row

typedef unsigned long long u64;

__device__ __forceinline__ u64 f2fma(u64 a, u64 b, u64 c) {
    u64 d; asm("fma.rn.f32x2 %0, %1, %2, %3;" : "=l"(d) : "l"(a), "l"(b), "l"(c)); return d;
}
__device__ __forceinline__ u64 f2add(u64 a, u64 b) {
    u64 d; asm("add.rn.f32x2 %0, %1, %2;" : "=l"(d) : "l"(a), "l"(b)); return d;
}
__device__ __forceinline__ u64 dup2(float x) {
    u64 r; asm("mov.b64 %0, {%1, %1};" : "=l"(r) : "f"(x)); return r;
}
__device__ __forceinline__ void up2(u64 v, float& lo, float& hi) {
    asm("mov.b64 {%0, %1}, %2;" : "=f"(lo), "=f"(hi) : "l"(v));
}
__device__ __forceinline__ uint32_t smem_u32(const void* p) {
    uint32_t a;
    asm("{ .reg .u64 t; cvta.to.shared.u64 t, %1; cvt.u32.u64 %0, t; }" : "=r"(a) : "l"(p));
    return a;
}
__device__ __forceinline__ void cpasync16(uint32_t saddr, const void* gptr) {
    asm volatile("cp.async.cg.shared.global [%0], [%1], 16;"
                 :: "r"(saddr), "l"(gptr) : "memory");
}
#define CP_COMMIT() asm volatile("cp.async.commit_group;" ::: "memory")
#define CP_WAIT0()  asm volatile("cp.async.wait_group 0;" ::: "memory")

// ---------------- scratch ----------------
__device__ float g_gi[(size_t)Lseq * G3 * Bsz];      // layer-0 input gates [t][3H][B]
__device__ float g_gi1[(size_t)Lseq * G3 * Bsz];     // layer-1 input gates [t][3H][B]
__device__ float g_hseq0[(size_t)Lseq * Hd * Bsz];   // [t][k][b]
__device__ float g_hseq1[(size_t)Lseq * Hd * Bsz];

__device__ unsigned g_flagA[4 * 32 * 32];   // layer-0 h progress (monotonic)
__device__ unsigned g_flagB[4 * 32 * 32];   // layer-1 h progress (monotonic)
__device__ unsigned g_giflag[Lseq * 12];    // gi1 tile-ready flags (== epoch)
__device__ unsigned g_epoch = 0;

__global__ void epoch_kernel() {
    if (threadIdx.x == 0 && blockIdx.x == 0) g_epoch = g_epoch + 1u;
}

// ---------------- input-side GEMM (layer 0): Gi[t][c][b] ----------------
__global__ __launch_bounds__(256) void gi_gemm_kernel(
    const float* __restrict__ xin, const float* __restrict__ W,
    const float* __restrict__ bias)
{
    __shared__ float Ws[16 * 132];
    __shared__ float As[16 * 132];

    const int t  = blockIdx.y;
    const int c0 = blockIdx.x * 128;
    const int tid = threadIdx.x;
    const int ty = tid >> 4;
    const int tx = tid & 15;

    u64 acc2[8][4];
#pragma unroll
    for (int i = 0; i < 8; i++)
#pragma unroll
        for (int j = 0; j < 4; j++) acc2[i][j] = 0ull;

    for (int k0 = 0; k0 < 256; k0 += 16) {
        {
            int row  = tid >> 2;
            int col4 = (tid & 3) * 4;
#pragma unroll
            for (int it = 0; it < 2; it++, row += 64) {
                float4 w = *(const float4*)(W + (size_t)(c0 + row) * 256 + k0 + col4);
                Ws[(col4 + 0) * 132 + row] = w.x;
                Ws[(col4 + 1) * 132 + row] = w.y;
                Ws[(col4 + 2) * 132 + row] = w.z;
                Ws[(col4 + 3) * 132 + row] = w.w;
            }
        }
        {
            int row  = tid >> 2;
            int col4 = (tid & 3) * 4;
#pragma unroll
            for (int it = 0; it < 2; it++, row += 64) {
                float4 a = *(const float4*)(xin + ((size_t)row * Lseq + t) * 256 + k0 + col4);
                As[(col4 + 0) * 132 + row] = a.x;
                As[(col4 + 1) * 132 + row] = a.y;
                As[(col4 + 2) * 132 + row] = a.z;
                As[(col4 + 3) * 132 + row] = a.w;
            }
        }
        __syncthreads();

#pragma unroll
        for (int kk = 0; kk < 16; kk++) {
            float wr[8];
            *(float4*)(wr)     = *(const float4*)(Ws + kk * 132 + ty * 4);
            *(float4*)(wr + 4) = *(const float4*)(Ws + kk * 132 + 64 + ty * 4);
            ulonglong2 aA = *(const ulonglong2*)(As + kk * 132 + tx * 4);
            ulonglong2 aB = *(const ulonglong2*)(As + kk * 132 + 64 + tx * 4);
#pragma unroll
            for (int i = 0; i < 8; i++) {
                u64 wd = dup2(wr[i]);
                acc2[i][0] = f2fma(aA.x, wd, acc2[i][0]);
                acc2[i][1] = f2fma(aA.y, wd, acc2[i][1]);
                acc2[i][2] = f2fma(aB.x, wd, acc2[i][2]);
                acc2[i][3] = f2fma(aB.y, wd, acc2[i][3]);
            }
        }
        __syncthreads();
    }

    float* gout = g_gi + (size_t)t * G3 * Bsz;
#pragma unroll
    for (int i = 0; i < 8; i++) {
        int c = (i < 4) ? (c0 + ty * 4 + i) : (c0 + 64 + ty * 4 + (i - 4));
        float bv = bias[c];
        float a0, a1, a2, a3, a4, a5, a6, a7;
        up2(acc2[i][0], a0, a1); up2(acc2[i][1], a2, a3);
        up2(acc2[i][2], a4, a5); up2(acc2[i][3], a6, a7);
        *(float4*)(gout + (size_t)c * Bsz + tx * 4) =
            make_float4(a0 + bv, a1 + bv, a2 + bv, a3 + bv);
        *(float4*)(gout + (size_t)c * Bsz + 64 + tx * 4) =
            make_float4(a4 + bv, a5 + bv, a6 + bv, a7 + bv);
    }
}

// ---------------- mega kernel: recur0 || recur1 || gemm1 ----------------
// bids 0-127:   layer-0 recurrence (dataflow flags, merged reduce+act)
// bids 128-255: layer-1 recurrence (gi from g_gi1, gated by g_giflag)
// bids 256+:    gemm1 scavenger tiles (gi1 = W_ih1 . h0(t) + b_ih1)
__global__ __launch_bounds__(512, 2) void gru_mega_kernel(
    const float* __restrict__ w_hh0, const float* __restrict__ b_hh0,
    const float* __restrict__ w_hh1, const float* __restrict__ b_hh1,
    const float* __restrict__ w_ih1, const float* __restrict__ b_ih1,
    const float* __restrict__ h0all)
{
    extern __shared__ __align__(16) char smraw[];
    const int tid = threadIdx.x;
    const unsigned E  = *(volatile unsigned*)&g_epoch;
    const unsigned FB = E * 2048u;

    if (blockIdx.x >= 256) {
        // ============ scavenger: gi1 tiles (64c x 128b x 4t) ============
        float* Ws = (float*)smraw;        // 16k x 64c, stride 68
        float* As = Ws + 16 * 68;         // 16k x 128b, stride 132
        const uint32_t As_addr = smem_u32(As);
        const int g  = (int)blockIdx.x - 256;
        const int ct = g % 12;
        const int tb = g / 12;
        const int c0s = ct * 64;
        const int ty = (tid & 255) >> 4;
        const int tx = tid & 15;

        for (int tt = 0; tt < 4; tt++) {
            const int t = tb * 4 + tt;
            if (tid < 128) {
                const unsigned* fp = &g_flagA[tid * 32];
                unsigned v;
                for (;;) {
                    asm volatile("ld.acquire.gpu.u32 %0, [%1];" : "=r"(v) : "l"(fp) : "memory");
                    if (v >= FB + (unsigned)(t + 1)) break;
                    __nanosleep(2000);
                }
            }
            __syncthreads();

            u64 acc2[4][4];
#pragma unroll
            for (int i = 0; i < 4; i++)
#pragma unroll
                for (int q = 0; q < 4; q++) acc2[i][q] = 0ull;

            const float* hsrc = g_hseq0 + (size_t)t * (Hd * Bsz);
            for (int k0 = 0; k0 < 256; k0 += 16) {
                // As via cp.async (one 16B per thread)
                {
                    int k = tid >> 5, b4 = (tid & 31) * 4;
                    cpasync16(As_addr + (uint32_t)(k * 132 + b4) * 4,
                              hsrc + (size_t)(k0 + k) * 128 + b4);
                }
                // Ws via float4 + scatter (threads 0-255)
                if (tid < 256) {
                    int row = tid >> 2, kk4 = (tid & 3) * 4;
                    float4 w = *(const float4*)(w_ih1 + (size_t)(c0s + row) * 256 + k0 + kk4);
                    Ws[(kk4 + 0) * 68 + row] = w.x;
                    Ws[(kk4 + 1) * 68 + row] = w.y;
                    Ws[(kk4 + 2) * 68 + row] = w.z;
                    Ws[(kk4 + 3) * 68 + row] = w.w;
                }
                CP_COMMIT();
                CP_WAIT0();
                __syncthreads();
                if (tid < 256) {
#pragma unroll
                    for (int kk = 0; kk < 16; kk++) {
                        float wr[4];
                        wr[0] = Ws[kk * 68 + ty * 4 + 0];
                        wr[1] = Ws[kk * 68 + ty * 4 + 1];
                        wr[2] = Ws[kk * 68 + ty * 4 + 2];
                        wr[3] = Ws[kk * 68 + ty * 4 + 3];
                        ulonglong2 aA = *(const ulonglong2*)(As + kk * 132 + tx * 4);
                        ulonglong2 aB = *(const ulonglong2*)(As + kk * 132 + 64 + tx * 4);
#pragma unroll
                        for (int i = 0; i < 4; i++) {
                            u64 wd = dup2(wr[i]);
                            acc2[i][0] = f2fma(aA.x, wd, acc2[i][0]);
                            acc2[i][1] = f2fma(aA.y, wd, acc2[i][1]);
                            acc2[i][2] = f2fma(aB.x, wd, acc2[i][2]);
                            acc2[i][3] = f2fma(aB.y, wd, acc2[i][3]);
                        }
                    }
                }
                __syncthreads();
            }
            if (tid < 256) {
                float* gout = g_gi1 + (size_t)t * (G3 * Bsz);
#pragma unroll
                for (int i = 0; i < 4; i++) {
                    int c = c0s + ty * 4 + i;
                    float bv = b_ih1[c];
                    float a0, a1, a2, a3, a4, a5, a6, a7;
                    up2(acc2[i][0], a0, a1); up2(acc2[i][1], a2, a3);
                    up2(acc2[i][2], a4, a5); up2(acc2[i][3], a6, a7);
                    *(float4*)(gout + (size_t)c * Bsz + tx * 4) =
                        make_float4(a0 + bv, a1 + bv, a2 + bv, a3 + bv);
                    *(float4*)(gout + (size_t)c * Bsz + 64 + tx * 4) =
                        make_float4(a4 + bv, a5 + bv, a6 + bv, a7 + bv);
                }
            }
            __syncthreads();
            if (tid == 0) {
                asm volatile("st.release.gpu.u32 [%0], %1;"
                             :: "l"(&g_giflag[t * 12 + ct]), "r"(E) : "memory");
            }
        }
        return;
    }

    // ============ recurrence (both layers) ============
    u64*   w2_s  = (u64*)smraw;            // 24*258 = 6192 u64
    u64*   red_s = w2_s + 6192;            // 8 kq * 384 = 3072 u64
    float* h_s   = (float*)(red_s + 3072); // 256 k * 32 b = 8192 floats
    float* bh_s  = h_s + 8192;             // 24 floats (+pad to 32)
    volatile unsigned* smflag = (volatile unsigned*)(bh_s + 32);  // 32 chunk flags
    const uint32_t h_addr = smem_u32(h_s);

    const int layer = (int)blockIdx.x >> 7;
    const int bid7  = (int)blockIdx.x & 127;
    const int bt = bid7 >> 5;
    const int ht = bid7 & 31;
    const int b0 = bt * 32;
    const int j0 = ht * 8;

    const float* w_hh = layer ? w_hh1 : w_hh0;
    const float* b_hh = layer ? b_hh1 : b_hh0;
    float* hseq = layer ? g_hseq1 : g_hseq0;
    unsigned* flags = layer ? g_flagB : g_flagA;
    unsigned* myflag = &flags[(bt * 32 + ht) * 32];
    const float* gi_src = layer ? g_gi1 : g_gi;

    const int ct0 = j0 >> 6;   // gi tile column (layer 1 gating)

    if (tid < 32) smflag[tid] = 0u;

    // duplicated persistent weights
    for (int idx = tid; idx < 6144; idx += 512) {
        int gj = idx >> 8;
        int k  = idx & 255;
        int g  = gj >> 3, j = gj & 7;
        w2_s[gj * W2S + k] = dup2(__ldg(w_hh + (size_t)(g * 256 + j0 + j) * 256 + k));
    }
    if (tid < 24) {
        int g = tid >> 3, j = tid & 7;
        bh_s[tid] = b_hh[g * 256 + j0 + j];
    }
    __syncthreads();

    const int bq = tid & 7;
    const int j  = (tid >> 3) & 7;
    const int kq = tid >> 6;
    const int kbase = kq * 32;
    const int warp = tid >> 5;
    const int lane = tid & 31;

    const u64* wrp = w2_s + (0 + j) * W2S + kbase;
    const u64* wzp = w2_s + (8 + j) * W2S + kbase;
    const u64* wnp = w2_s + (16 + j) * W2S + kbase;
    const float* hb = h_s + kbase * 32 + bq * 4;

    // merged reduce+act mapping (tid < 128): aj = hidden unit, bp = batch pair
    const int aj = tid >> 4;
    const int bp = tid & 15;
    const size_t gidx2 = (size_t)(j0 + aj) * Bsz + b0 + 2 * bp;

    float2 cir2 = make_float2(0.f, 0.f), ciz2 = cir2, cin2 = cir2;
    if (tid < 128) {
        if (layer) {
            unsigned v;
#pragma unroll
            for (int e = 0; e < 3; e++) {
                const unsigned* fp = &g_giflag[0 * 12 + 4 * e + ct0];
                do {
                    asm volatile("ld.acquire.gpu.u32 %0, [%1];" : "=r"(v) : "l"(fp) : "memory");
                } while (v < E);
            }
        }
        cir2 = *(const float2*)(gi_src + gidx2);
        ciz2 = *(const float2*)(gi_src + 32768 + gidx2);
        cin2 = *(const float2*)(gi_src + 65536 + gidx2);
    }

    for (int t = 0; t < Lseq; t++) {
        // ---- stage h(t-1) ----
        if (t == 0) {
            const float* h0g = h0all + (size_t)layer * Bsz * Hd;  // [b][k]
            for (int i = tid; i < 8192; i += 512) {
                int k = i >> 5, bb = i & 31;
                h_s[k * 32 + bb] = h0g[(size_t)(b0 + bb) * 256 + k];
            }
            __syncthreads();
        } else {
            const float* src = hseq + (size_t)(t - 1) * (Hd * Bsz);
            const int kq_w = warp >> 1;
            const int c0c = kq_w * 4 + (warp & 1) * 2;   // first of 2 chunks
            // poll both producer flags, then one cp.async batch
#pragma unroll
            for (int e = 0; e < 2; e++) {
                const unsigned* fp = &flags[(bt * 32 + c0c + e) * 32];
                unsigned v;
                do {
                    asm volatile("ld.acquire.gpu.u32 %0, [%1];" : "=r"(v) : "l"(fp) : "memory");
                } while (v < FB + (unsigned)t);
            }
#pragma unroll
            for (int e = 0; e < 2; e++) {
                int k   = (c0c + e) * 8 + (lane >> 2);
                int col = (lane & 3) * 4;
                const float* sp = src + (size_t)k * Bsz + b0 + col;
                cpasync16(h_addr + (uint32_t)(k * 32 + col) * 4, sp);
                cpasync16(h_addr + (uint32_t)(k * 32 + col + 16) * 4, sp + 16);
            }
            CP_COMMIT();
            CP_WAIT0();
            __syncwarp();
            __threadfence_block();
            if (lane == 0) {
                smflag[c0c]     = (unsigned)t;
                smflag[c0c + 1] = (unsigned)t;
            }
            // wait for all 4 chunks this thread's dot needs
#pragma unroll
            for (int e = 0; e < 4; e++) {
                int c = kq * 4 + e;
                while (smflag[c] < (unsigned)t) { }
            }
            __threadfence_block();
        }

        // ---- partial dot over this thread's 32 k (f32x2 over batch) ----
        u64 ar0 = 0, ar1 = 0, az0 = 0, az1 = 0, an0 = 0, an1 = 0;
#pragma unroll
        for (int i = 0; i < 32; i += 2) {
            ulonglong2 ha = *(const ulonglong2*)(hb + i * 32);
            ulonglong2 hc = *(const ulonglong2*)(hb + i * 32 + 32);
            ulonglong2 wr = *(const ulonglong2*)(wrp + i);
            ulonglong2 wz = *(const ulonglong2*)(wzp + i);
            ulonglong2 wn = *(const ulonglong2*)(wnp + i);
            ar0 = f2fma(ha.x, wr.x, ar0); ar1 = f2fma(ha.y, wr.x, ar1);
            ar0 = f2fma(hc.x, wr.y, ar0); ar1 = f2fma(hc.y, wr.y, ar1);
            az0 = f2fma(ha.x, wz.x, az0); az1 = f2fma(ha.y, wz.x, az1);
            az0 = f2fma(hc.x, wz.y, az0); az1 = f2fma(hc.y, wz.y, az1);
            an0 = f2fma(ha.x, wn.x, an0); an1 = f2fma(ha.y, wn.x, an1);
            an0 = f2fma(hc.x, wn.y, an0); an1 = f2fma(hc.y, wn.y, an1);
        }
        {
            u64* rb = red_s + (size_t)kq * 384 + (j * 8 + bq) * 2;
            *(ulonglong2*)(rb)       = make_ulonglong2(ar0, ar1);
            *(ulonglong2*)(rb + 128) = make_ulonglong2(az0, az1);
            *(ulonglong2*)(rb + 256) = make_ulonglong2(an0, an1);
        }
        __syncthreads();

        // ---- merged reduce + activation (128 threads: 8 j x 16 b-pairs) ----
        if (tid < 128) {
            const u64* base = red_s + aj * 16 + bp;
            u64 sr = 0, sz = 0, sn = 0;
#pragma unroll
            for (int q = 0; q < 8; q++) {
                sr = f2add(sr, base[q * 384]);
                sz = f2add(sz, base[q * 384 + 128]);
                sn = f2add(sn, base[q * 384 + 256]);
            }
            float gr0, gr1, gz0, gz1, gn0, gn1;
            up2(sr, gr0, gr1); up2(sz, gz0, gz1); up2(sn, gn0, gn1);
            float bhr = bh_s[aj], bhz = bh_s[8 + aj], bhn = bh_s[16 + aj];

            float2 hp = *(const float2*)(h_s + (j0 + aj) * 32 + 2 * bp);

            float r0 = 1.0f / (1.0f + __expf(-(cir2.x + gr0 + bhr)));
            float r1 = 1.0f / (1.0f + __expf(-(cir2.y + gr1 + bhr)));
            float z0 = 1.0f / (1.0f + __expf(-(ciz2.x + gz0 + bhz)));
            float z1 = 1.0f / (1.0f + __expf(-(ciz2.y + gz1 + bhz)));
            float n0 = tanhf(cin2.x + r0 * (gn0 + bhn));
            float n1 = tanhf(cin2.y + r1 * (gn1 + bhn));
            float hn0 = (1.0f - z0) * n0 + z0 * hp.x;
            float hn1 = (1.0f - z1) * n1 + z1 * hp.y;

            *(float2*)(hseq + (size_t)t * (Hd * Bsz) + gidx2) = make_float2(hn0, hn1);
        }
        __syncthreads();

        if (tid == 0) {
            asm volatile("st.release.gpu.u32 [%0], %1;"
                         :: "l"(myflag), "r"(FB + (unsigned)(t + 1)) : "memory");
        }
        if (tid < 128 && t + 1 < Lseq) {
            if (layer) {
                unsigned v;
#pragma unroll
                for (int e = 0; e < 3; e++) {
                    const unsigned* fp = &g_giflag[(t + 1) * 12 + 4 * e + ct0];
                    do {
                        asm volatile("ld.acquire.gpu.u32 %0, [%1];" : "=r"(v) : "l"(fp) : "memory");
                    } while (v < E);
                }
            }
            const float* gi_n = gi_src + (size_t)(t + 1) * (G3 * Bsz);
            cir2 = *(const float2*)(gi_n + gidx2);
            ciz2 = *(const float2*)(gi_n + 32768 + gidx2);
            cin2 = *(const float2*)(gi_n + 65536 + gidx2);
        }
    }
}

// ---------------- transpose g_hseq1 [t][h][b] -> out [b][t][h] ----------------
__global__ __launch_bounds__(256) void transpose_out_kernel(float* __restrict__ out)
{
    __shared__ float tile[32 * 129];
    const int t  = blockIdx.y;
    const int h0 = blockIdx.x * 32;
    const int tid = threadIdx.x;
    const float* src = g_hseq1 + (size_t)t * (Hd * Bsz) + (size_t)h0 * Bsz;

    for (int idx = tid; idx < 4096; idx += 256) {
        int hh = idx >> 7, bb = idx & 127;
        tile[hh * 129 + bb] = src[idx];
    }
    __syncthreads();
    for (int idx = tid; idx < 4096; idx += 256) {
        int bb = idx >> 5, hh = idx & 31;
        out[(size_t)bb * Lseq * Hd + (size_t)t * Hd + h0 + hh] = tile[hh * 129 + bb];
    }
}

// ---------------- final hidden states ----------------
__global__ __launch_bounds__(256) void hn_kernel(float* __restrict__ out)
{
    int idx = blockIdx.x * blockDim.x + threadIdx.x;  // 0..65535
    int layer = idx >> 15;
    int b = (idx >> 8) & 127;
    int h = idx & 255;
    const float* hs = layer ? g_hseq1 : g_hseq0;
    out[(size_t)Bsz * Lseq * Hd + idx] =
        hs[(size_t)(Lseq - 1) * (Hd * Bsz) + (size_t)h * Bsz + b];
}

// ---------------- launcher ----------------
extern "C" void kernel_launch(void* const* d_in, const int* in_sizes, int n_in,
                              void* d_out, int out_size)
{
    const float* x     = (const float*)d_in[0];
    const float* h0    = (const float*)d_in[1];
    const float* w_ih0 = (const float*)d_in[2];
    const float* w_hh0 = (const float*)d_in[3];
    const float* b_ih0 = (const float*)d_in[4];
    const float* b_hh0 = (const float*)d_in[5];
    const float* w_ih1 = (const float*)d_in[6];
    const float* w_hh1 = (const float*)d_in[7];
    const float* b_ih1 = (const float*)d_in[8];
    const float* b_hh1 = (const float*)d_in[9];
    float* out = (float*)d_out;

    const size_t smem = (6192 + 3072) * sizeof(u64)
                      + (8192 + 32) * sizeof(float)
                      + 32 * sizeof(unsigned);   // 107,136 B -> 2 blocks/SM
    cudaFuncSetAttribute(gru_mega_kernel,
                         cudaFuncAttributeMaxDynamicSharedMemorySize, (int)smem);

    epoch_kernel<<<1, 32>>>();
    gi_gemm_kernel<<<dim3(6, Lseq), 256>>>(x, w_ih0, b_ih0);
    // recur0 (0-127) || recur1 (128-255) || gemm1 scavengers (256..3327)
    gru_mega_kernel<<<256 + 3072, 512, smem>>>(w_hh0, b_hh0, w_hh1, b_hh1,
                                               w_ih1, b_ih1, h0);
    transpose_out_kernel<<<dim3(8, Lseq), 256>>>(out);
    if (out_size >= (int)((size_t)Bsz * Lseq * Hd + 2 * Bsz * Hd))
        hn_kernel<<<256, 256>>>(out);
}

// round 17
// speedup vs baseline: 1.3200x; 1.0091x over previous
#include <cuda_runtime.h>
#include <cstdint>

#define Bsz 128
#define Lseq 1024
#define Hd 256
#define G3 768
#define W2S 258   // u64 stride per duplicated-weight row

typedef unsigned long long u64;

__device__ __forceinline__ u64 f2fma(u64 a, u64 b, u64 c) {
    u64 d; asm("fma.rn.f32x2 %0, %1, %2, %3;" : "=l"(d) : "l"(a), "l"(b), "l"(c)); return d;
}
__device__ __forceinline__ u64 f2add(u64 a, u64 b) {
    u64 d; asm("add.rn.f32x2 %0, %1, %2;" : "=l"(d) : "l"(a), "l"(b)); return d;
}
__device__ __forceinline__ u64 dup2(float x) {
    u64 r; asm("mov.b64 %0, {%1, %1};" : "=l"(r) : "f"(x)); return r;
}
__device__ __forceinline__ void up2(u64 v, float& lo, float& hi) {
    asm("mov.b64 {%0, %1}, %2;" : "=f"(lo), "=f"(hi) : "l"(v));
}
__device__ __forceinline__ uint32_t smem_u32(const void* p) {
    uint32_t a;
    asm("{ .reg .u64 t; cvta.to.shared.u64 t, %1; cvt.u32.u64 %0, t; }" : "=r"(a) : "l"(p));
    return a;
}
__device__ __forceinline__ void cpasync16(uint32_t saddr, const void* gptr) {
    asm volatile("cp.async.cg.shared.global [%0], [%1], 16;"
                 :: "r"(saddr), "l"(gptr) : "memory");
}
#define CP_COMMIT() asm volatile("cp.async.commit_group;" ::: "memory")
#define CP_WAIT0()  asm volatile("cp.async.wait_group 0;" ::: "memory")

// ---------------- scratch ----------------
__device__ float g_gi[(size_t)Lseq * G3 * Bsz];      // layer-0 input gates [t][3H][B]
__device__ float g_gi1[(size_t)Lseq * G3 * Bsz];     // layer-1 input gates [t][3H][B]
__device__ float g_hseq0[(size_t)Lseq * Hd * Bsz];   // [t][k][b]
__device__ float g_hseq1[(size_t)Lseq * Hd * Bsz];

__device__ unsigned g_flagA[4 * 32 * 32];   // layer-0 h progress (monotonic)
__device__ unsigned g_flagB[4 * 32 * 32];   // layer-1 h progress (monotonic)
__device__ unsigned g_giflag[Lseq * 12];    // gi1 tile-ready flags (== epoch)
__device__ unsigned g_epoch = 0;

__global__ void epoch_kernel() {
    if (threadIdx.x == 0 && blockIdx.x == 0) g_epoch = g_epoch + 1u;
}

// ---------------- input-side GEMM (layer 0): Gi[t][c][b] ----------------
__global__ __launch_bounds__(256) void gi_gemm_kernel(
    const float* __restrict__ xin, const float* __restrict__ W,
    const float* __restrict__ bias)
{
    __shared__ float Ws[16 * 132];
    __shared__ float As[16 * 132];

    const int t  = blockIdx.y;
    const int c0 = blockIdx.x * 128;
    const int tid = threadIdx.x;
    const int ty = tid >> 4;
    const int tx = tid & 15;

    u64 acc2[8][4];
#pragma unroll
    for (int i = 0; i < 8; i++)
#pragma unroll
        for (int j = 0; j < 4; j++) acc2[i][j] = 0ull;

    for (int k0 = 0; k0 < 256; k0 += 16) {
        {
            int row  = tid >> 2;
            int col4 = (tid & 3) * 4;
#pragma unroll
            for (int it = 0; it < 2; it++, row += 64) {
                float4 w = *(const float4*)(W + (size_t)(c0 + row) * 256 + k0 + col4);
                Ws[(col4 + 0) * 132 + row] = w.x;
                Ws[(col4 + 1) * 132 + row] = w.y;
                Ws[(col4 + 2) * 132 + row] = w.z;
                Ws[(col4 + 3) * 132 + row] = w.w;
            }
        }
        {
            int row  = tid >> 2;
            int col4 = (tid & 3) * 4;
#pragma unroll
            for (int it = 0; it < 2; it++, row += 64) {
                float4 a = *(const float4*)(xin + ((size_t)row * Lseq + t) * 256 + k0 + col4);
                As[(col4 + 0) * 132 + row] = a.x;
                As[(col4 + 1) * 132 + row] = a.y;
                As[(col4 + 2) * 132 + row] = a.z;
                As[(col4 + 3) * 132 + row] = a.w;
            }
        }
        __syncthreads();

#pragma unroll
        for (int kk = 0; kk < 16; kk++) {
            float wr[8];
            *(float4*)(wr)     = *(const float4*)(Ws + kk * 132 + ty * 4);
            *(float4*)(wr + 4) = *(const float4*)(Ws + kk * 132 + 64 + ty * 4);
            ulonglong2 aA = *(const ulonglong2*)(As + kk * 132 + tx * 4);
            ulonglong2 aB = *(const ulonglong2*)(As + kk * 132 + 64 + tx * 4);
#pragma unroll
            for (int i = 0; i < 8; i++) {
                u64 wd = dup2(wr[i]);
                acc2[i][0] = f2fma(aA.x, wd, acc2[i][0]);
                acc2[i][1] = f2fma(aA.y, wd, acc2[i][1]);
                acc2[i][2] = f2fma(aB.x, wd, acc2[i][2]);
                acc2[i][3] = f2fma(aB.y, wd, acc2[i][3]);
            }
        }
        __syncthreads();
    }

    float* gout = g_gi + (size_t)t * G3 * Bsz;
#pragma unroll
    for (int i = 0; i < 8; i++) {
        int c = (i < 4) ? (c0 + ty * 4 + i) : (c0 + 64 + ty * 4 + (i - 4));
        float bv = bias[c];
        float a0, a1, a2, a3, a4, a5, a6, a7;
        up2(acc2[i][0], a0, a1); up2(acc2[i][1], a2, a3);
        up2(acc2[i][2], a4, a5); up2(acc2[i][3], a6, a7);
        *(float4*)(gout + (size_t)c * Bsz + tx * 4) =
            make_float4(a0 + bv, a1 + bv, a2 + bv, a3 + bv);
        *(float4*)(gout + (size_t)c * Bsz + 64 + tx * 4) =
            make_float4(a4 + bv, a5 + bv, a6 + bv, a7 + bv);
    }
}

// ---------------- mega kernel: recur0 || recur1 || gemm1 ----------------
__global__ __launch_bounds__(512, 2) void gru_mega_kernel(
    const float* __restrict__ w_hh0, const float* __restrict__ b_hh0,
    const float* __restrict__ w_hh1, const float* __restrict__ b_hh1,
    const float* __restrict__ w_ih1, const float* __restrict__ b_ih1,
    const float* __restrict__ h0all)
{
    extern __shared__ __align__(16) char smraw[];
    const int tid = threadIdx.x;
    const unsigned E  = *(volatile unsigned*)&g_epoch;
    const unsigned FB = E * 2048u;

    if (blockIdx.x >= 256) {
        // ============ scavenger: gi1 tiles (64c x 128b x 4t) ============
        float* Ws = (float*)smraw;        // 16k x 64c, stride 68
        float* As = Ws + 16 * 68;         // 16k x 128b, stride 132
        const uint32_t As_addr = smem_u32(As);
        const int g  = (int)blockIdx.x - 256;
        const int ct = g % 12;
        const int tb = g / 12;
        const int c0s = ct * 64;
        const int ty = (tid & 255) >> 4;
        const int tx = tid & 15;

        for (int tt = 0; tt < 4; tt++) {
            const int t = tb * 4 + tt;
            if (tid < 128) {
                const unsigned* fp = &g_flagA[tid * 32];
                unsigned v;
                for (;;) {
                    asm volatile("ld.acquire.gpu.u32 %0, [%1];" : "=r"(v) : "l"(fp) : "memory");
                    if (v >= FB + (unsigned)(t + 1)) break;
                    __nanosleep(2000);
                }
            }
            __syncthreads();

            u64 acc2[4][4];
#pragma unroll
            for (int i = 0; i < 4; i++)
#pragma unroll
                for (int q = 0; q < 4; q++) acc2[i][q] = 0ull;

            const float* hsrc = g_hseq0 + (size_t)t * (Hd * Bsz);
            for (int k0 = 0; k0 < 256; k0 += 16) {
                {
                    int k = tid >> 5, b4 = (tid & 31) * 4;
                    cpasync16(As_addr + (uint32_t)(k * 132 + b4) * 4,
                              hsrc + (size_t)(k0 + k) * 128 + b4);
                }
                if (tid < 256) {
                    int row = tid >> 2, kk4 = (tid & 3) * 4;
                    float4 w = *(const float4*)(w_ih1 + (size_t)(c0s + row) * 256 + k0 + kk4);
                    Ws[(kk4 + 0) * 68 + row] = w.x;
                    Ws[(kk4 + 1) * 68 + row] = w.y;
                    Ws[(kk4 + 2) * 68 + row] = w.z;
                    Ws[(kk4 + 3) * 68 + row] = w.w;
                }
                CP_COMMIT();
                CP_WAIT0();
                __syncthreads();
                if (tid < 256) {
#pragma unroll
                    for (int kk = 0; kk < 16; kk++) {
                        float wr[4];
                        wr[0] = Ws[kk * 68 + ty * 4 + 0];
                        wr[1] = Ws[kk * 68 + ty * 4 + 1];
                        wr[2] = Ws[kk * 68 + ty * 4 + 2];
                        wr[3] = Ws[kk * 68 + ty * 4 + 3];
                        ulonglong2 aA = *(const ulonglong2*)(As + kk * 132 + tx * 4);
                        ulonglong2 aB = *(const ulonglong2*)(As + kk * 132 + 64 + tx * 4);
#pragma unroll
                        for (int i = 0; i < 4; i++) {
                            u64 wd = dup2(wr[i]);
                            acc2[i][0] = f2fma(aA.x, wd, acc2[i][0]);
                            acc2[i][1] = f2fma(aA.y, wd, acc2[i][1]);
                            acc2[i][2] = f2fma(aB.x, wd, acc2[i][2]);
                            acc2[i][3] = f2fma(aB.y, wd, acc2[i][3]);
                        }
                    }
                }
                __syncthreads();
            }
            if (tid < 256) {
                float* gout = g_gi1 + (size_t)t * (G3 * Bsz);
#pragma unroll
                for (int i = 0; i < 4; i++) {
                    int c = c0s + ty * 4 + i;
                    float bv = b_ih1[c];
                    float a0, a1, a2, a3, a4, a5, a6, a7;
                    up2(acc2[i][0], a0, a1); up2(acc2[i][1], a2, a3);
                    up2(acc2[i][2], a4, a5); up2(acc2[i][3], a6, a7);
                    *(float4*)(gout + (size_t)c * Bsz + tx * 4) =
                        make_float4(a0 + bv, a1 + bv, a2 + bv, a3 + bv);
                    *(float4*)(gout + (size_t)c * Bsz + 64 + tx * 4) =
                        make_float4(a4 + bv, a5 + bv, a6 + bv, a7 + bv);
                }
            }
            __syncthreads();
            if (tid == 0) {
                asm volatile("st.release.gpu.u32 [%0], %1;"
                             :: "l"(&g_giflag[t * 12 + ct]), "r"(E) : "memory");
            }
        }
        return;
    }

    // ============ recurrence (both layers) ============
    u64*   w2_s  = (u64*)smraw;            // 24*258 = 6192 u64
    u64*   red_s = w2_s + 6192;            // 8 kq * 384 = 3072 u64
    float* h_s   = (float*)(red_s + 3072); // 256 k * 32 b = 8192 floats
    float* bh_s  = h_s + 8192;             // 24 floats (+pad to 32)
    volatile unsigned* smflag = (volatile unsigned*)(bh_s + 32);  // 32 chunk flags
    volatile unsigned* act_ep = smflag + 32;                      // act epoch
    const uint32_t h_addr = smem_u32(h_s);

    const int layer = (int)blockIdx.x >> 7;
    const int bid7  = (int)blockIdx.x & 127;
    const int bt = bid7 >> 5;
    const int ht = bid7 & 31;
    const int b0 = bt * 32;
    const int j0 = ht * 8;

    const float* w_hh = layer ? w_hh1 : w_hh0;
    const float* b_hh = layer ? b_hh1 : b_hh0;
    float* hseq = layer ? g_hseq1 : g_hseq0;
    unsigned* flags = layer ? g_flagB : g_flagA;
    unsigned* myflag = &flags[(bt * 32 + ht) * 32];
    const float* gi_src = layer ? g_gi1 : g_gi;
    const float* h0g = h0all + (size_t)layer * Bsz * Hd;  // [b][k]

    const int ct0 = j0 >> 6;   // gi tile column (layer 1 gating)

    if (tid < 32) smflag[tid] = 0u;
    if (tid == 32) *act_ep = 0u;

    // duplicated persistent weights
    for (int idx = tid; idx < 6144; idx += 512) {
        int gj = idx >> 8;
        int k  = idx & 255;
        int g  = gj >> 3, j = gj & 7;
        w2_s[gj * W2S + k] = dup2(__ldg(w_hh + (size_t)(g * 256 + j0 + j) * 256 + k));
    }
    if (tid < 24) {
        int g = tid >> 3, j = tid & 7;
        bh_s[tid] = b_hh[g * 256 + j0 + j];
    }
    __syncthreads();

    const int bq = tid & 7;
    const int j  = (tid >> 3) & 7;
    const int kq = tid >> 6;
    const int kbase = kq * 32;
    const int warp = tid >> 5;
    const int lane = tid & 31;

    const u64* wrp = w2_s + (0 + j) * W2S + kbase;
    const u64* wzp = w2_s + (8 + j) * W2S + kbase;
    const u64* wnp = w2_s + (16 + j) * W2S + kbase;
    const float* hb = h_s + kbase * 32 + bq * 4;

    // merged reduce+act mapping (tid < 128)
    const int aj = tid >> 4;
    const int bp = tid & 15;
    const size_t gidx2 = (size_t)(j0 + aj) * Bsz + b0 + 2 * bp;

    float2 cir2 = make_float2(0.f, 0.f), ciz2 = cir2, cin2 = cir2;
    float2 hprev2 = make_float2(0.f, 0.f);
    if (tid < 128) {
        if (layer) {
            unsigned v;
#pragma unroll
            for (int e = 0; e < 3; e++) {
                const unsigned* fp = &g_giflag[0 * 12 + 4 * e + ct0];
                for (;;) {
                    asm volatile("ld.acquire.gpu.u32 %0, [%1];" : "=r"(v) : "l"(fp) : "memory");
                    if (v >= E) break;
                    __nanosleep(300);
                }
            }
        }
        cir2 = *(const float2*)(gi_src + gidx2);
        ciz2 = *(const float2*)(gi_src + 32768 + gidx2);
        cin2 = *(const float2*)(gi_src + 65536 + gidx2);
        // h_prev registers from h0
        hprev2.x = h0g[(size_t)(b0 + 2 * bp) * 256 + j0 + aj];
        hprev2.y = h0g[(size_t)(b0 + 2 * bp + 1) * 256 + j0 + aj];
    }

    for (int t = 0; t < Lseq; t++) {
        // ---- stage h(t-1) ----
        if (t == 0) {
            for (int i = tid; i < 8192; i += 512) {
                int k = i >> 5, bb = i & 31;
                h_s[k * 32 + bb] = h0g[(size_t)(b0 + bb) * 256 + k];
            }
            __syncthreads();
        } else {
            const float* src = hseq + (size_t)(t - 1) * (Hd * Bsz);
            const int kq_w = warp >> 1;
            const int c0c = kq_w * 4 + (warp & 1) * 2;   // this warp's 2 chunks
#pragma unroll
            for (int e = 0; e < 2; e++) {
                const unsigned* fp = &flags[(bt * 32 + c0c + e) * 32];
                unsigned v;
                do {
                    asm volatile("ld.acquire.gpu.u32 %0, [%1];" : "=r"(v) : "l"(fp) : "memory");
                } while (v < FB + (unsigned)t);
            }
#pragma unroll
            for (int e = 0; e < 2; e++) {
                int k   = (c0c + e) * 8 + (lane >> 2);
                int col = (lane & 3) * 4;
                const float* sp = src + (size_t)k * Bsz + b0 + col;
                cpasync16(h_addr + (uint32_t)(k * 32 + col) * 4, sp);
                cpasync16(h_addr + (uint32_t)(k * 32 + col + 16) * 4, sp + 16);
            }
            CP_COMMIT();
            CP_WAIT0();
            __syncwarp();
            __threadfence_block();
            if (lane == 0) {
                smflag[c0c]     = (unsigned)t;
                smflag[c0c + 1] = (unsigned)t;
            }
#pragma unroll
            for (int e = 0; e < 4; e++) {
                int c = kq * 4 + e;
                while (smflag[c] < (unsigned)t) { }
            }
            __threadfence_block();
        }

        // red_s hazard guard: previous step's act must have finished
        if (t > 0) {
            while (*act_ep < (unsigned)t) { }
        }

        // ---- partial dot over this thread's 32 k (f32x2 over batch) ----
        u64 ar0 = 0, ar1 = 0, az0 = 0, az1 = 0, an0 = 0, an1 = 0;
#pragma unroll
        for (int i = 0; i < 32; i += 2) {
            ulonglong2 ha = *(const ulonglong2*)(hb + i * 32);
            ulonglong2 hc = *(const ulonglong2*)(hb + i * 32 + 32);
            ulonglong2 wr = *(const ulonglong2*)(wrp + i);
            ulonglong2 wz = *(const ulonglong2*)(wzp + i);
            ulonglong2 wn = *(const ulonglong2*)(wnp + i);
            ar0 = f2fma(ha.x, wr.x, ar0); ar1 = f2fma(ha.y, wr.x, ar1);
            ar0 = f2fma(hc.x, wr.y, ar0); ar1 = f2fma(hc.y, wr.y, ar1);
            az0 = f2fma(ha.x, wz.x, az0); az1 = f2fma(ha.y, wz.x, az1);
            az0 = f2fma(hc.x, wz.y, az0); az1 = f2fma(hc.y, wz.y, az1);
            an0 = f2fma(ha.x, wn.x, an0); an1 = f2fma(ha.y, wn.x, an1);
            an0 = f2fma(hc.x, wn.y, an0); an1 = f2fma(hc.y, wn.y, an1);
        }
        {
            u64* rb = red_s + (size_t)kq * 384 + (j * 8 + bq) * 2;
            *(ulonglong2*)(rb)       = make_ulonglong2(ar0, ar1);
            *(ulonglong2*)(rb + 128) = make_ulonglong2(az0, az1);
            *(ulonglong2*)(rb + 256) = make_ulonglong2(an0, an1);
        }
        __syncthreads();

        // ---- merged reduce + activation (warps 0-3 only); other warps run ahead ----
        if (tid < 128) {
            const u64* base = red_s + aj * 16 + bp;
            u64 sr = 0, sz = 0, sn = 0;
#pragma unroll
            for (int q = 0; q < 8; q++) {
                sr = f2add(sr, base[q * 384]);
                sz = f2add(sz, base[q * 384 + 128]);
                sn = f2add(sn, base[q * 384 + 256]);
            }
            float gr0, gr1, gz0, gz1, gn0, gn1;
            up2(sr, gr0, gr1); up2(sz, gz0, gz1); up2(sn, gn0, gn1);
            float bhr = bh_s[aj], bhz = bh_s[8 + aj], bhn = bh_s[16 + aj];

            float r0 = 1.0f / (1.0f + __expf(-(cir2.x + gr0 + bhr)));
            float r1 = 1.0f / (1.0f + __expf(-(cir2.y + gr1 + bhr)));
            float z0 = 1.0f / (1.0f + __expf(-(ciz2.x + gz0 + bhz)));
            float z1 = 1.0f / (1.0f + __expf(-(ciz2.y + gz1 + bhz)));
            float n0 = tanhf(cin2.x + r0 * (gn0 + bhn));
            float n1 = tanhf(cin2.y + r1 * (gn1 + bhn));
            float hn0 = (1.0f - z0) * n0 + z0 * hprev2.x;
            float hn1 = (1.0f - z1) * n1 + z1 * hprev2.y;
            hprev2 = make_float2(hn0, hn1);

            *(float2*)(hseq + (size_t)t * (Hd * Bsz) + gidx2) = make_float2(hn0, hn1);

            asm volatile("bar.sync 1, 128;" ::: "memory");
            if (tid == 0) {
                *act_ep = (unsigned)(t + 1);
                asm volatile("st.release.gpu.u32 [%0], %1;"
                             :: "l"(myflag), "r"(FB + (unsigned)(t + 1)) : "memory");
            }
            // prefetch next-step gi
            if (t + 1 < Lseq) {
                if (layer) {
                    unsigned v;
#pragma unroll
                    for (int e = 0; e < 3; e++) {
                        const unsigned* fp = &g_giflag[(t + 1) * 12 + 4 * e + ct0];
                        for (;;) {
                            asm volatile("ld.acquire.gpu.u32 %0, [%1];" : "=r"(v) : "l"(fp) : "memory");
                            if (v >= E) break;
                            __nanosleep(300);
                        }
                    }
                }
                const float* gi_n = gi_src + (size_t)(t + 1) * (G3 * Bsz);
                cir2 = *(const float2*)(gi_n + gidx2);
                ciz2 = *(const float2*)(gi_n + 32768 + gidx2);
                cin2 = *(const float2*)(gi_n + 65536 + gidx2);
            }
        }
    }
}

// ---------------- transpose g_hseq1 [t][h][b] -> out [b][t][h] ----------------
__global__ __launch_bounds__(256) void transpose_out_kernel(float* __restrict__ out)
{
    __shared__ float tile[32 * 129];
    const int t  = blockIdx.y;
    const int h0 = blockIdx.x * 32;
    const int tid = threadIdx.x;
    const float* src = g_hseq1 + (size_t)t * (Hd * Bsz) + (size_t)h0 * Bsz;

    for (int idx = tid; idx < 4096; idx += 256) {
        int hh = idx >> 7, bb = idx & 127;
        tile[hh * 129 + bb] = src[idx];
    }
    __syncthreads();
    for (int idx = tid; idx < 4096; idx += 256) {
        int bb = idx >> 5, hh = idx & 31;
        out[(size_t)bb * Lseq * Hd + (size_t)t * Hd + h0 + hh] = tile[hh * 129 + bb];
    }
}

// ---------------- final hidden states ----------------
__global__ __launch_bounds__(256) void hn_kernel(float* __restrict__ out)
{
    int idx = blockIdx.x * blockDim.x + threadIdx.x;  // 0..65535
    int layer = idx >> 15;
    int b = (idx >> 8) & 127;
    int h = idx & 255;
    const float* hs = layer ? g_hseq1 : g_hseq0;
    out[(size_t)Bsz * Lseq * Hd + idx] =
        hs[(size_t)(Lseq - 1) * (Hd * Bsz) + (size_t)h * Bsz + b];
}

// ---------------- launcher ----------------
extern "C" void kernel_launch(void* const* d_in, const int* in_sizes, int n_in,
                              void* d_out, int out_size)
{
    const float* x     = (const float*)d_in[0];
    const float* h0    = (const float*)d_in[1];
    const float* w_ih0 = (const float*)d_in[2];
    const float* w_hh0 = (const float*)d_in[3];
    const float* b_ih0 = (const float*)d_in[4];
    const float* b_hh0 = (const float*)d_in[5];
    const float* w_ih1 = (const float*)d_in[6];
    const float* w_hh1 = (const float*)d_in[7];
    const float* b_ih1 = (const float*)d_in[8];
    const float* b_hh1 = (const float*)d_in[9];
    float* out = (float*)d_out;

    const size_t smem = (6192 + 3072) * sizeof(u64)
                      + (8192 + 32) * sizeof(float)
                      + 64 * sizeof(unsigned);   // ~107.3 KB -> 2 blocks/SM
    cudaFuncSetAttribute(gru_mega_kernel,
                         cudaFuncAttributeMaxDynamicSharedMemorySize, (int)smem);

    epoch_kernel<<<1, 32>>>();
    gi_gemm_kernel<<<dim3(6, Lseq), 256>>>(x, w_ih0, b_ih0);
    gru_mega_kernel<<<256 + 3072, 512, smem>>>(w_hh0, b_hh0, w_hh1, b_hh1,
                                               w_ih1, b_ih1, h0);
    transpose_out_kernel<<<dim3(8, Lseq), 256>>>(out);
    if (out_size >= (int)((size_t)Bsz * Lseq * Hd + 2 * Bsz * Hd))
        hn_kernel<<<256, 256>>>(out);
}